// round 15
// baseline (speedup 1.0000x reference)
#include <cuda_runtime.h>
#include <cuda_fp16.h>
#include <math.h>
#include <stdint.h>

#define BATCH 2
#define NSEQ  2048
#define DIM   1024
#define HEADS 16
#define DHEAD 64
#define INNER 1024
#define ROWS  (BATCH*NSEQ)   // 4096
#define QKVW  (3*INNER)      // 3072
#define LN_EPS 1e-5f

// Scratch (static device allocations — allowed)
__device__ __half g_xn_h  [(size_t)ROWS * DIM  ];
__device__ __half g_qkv_h [(size_t)ROWS * QKVW ];
__device__ __half g_oat_h [(size_t)ROWS * INNER];
__device__ __half g_wqkvh [(size_t)DIM * QKVW ];   // row-major [K, N] fp16
__device__ __half g_wouth [(size_t)INNER * DIM ];  // row-major [K, N] fp16

// ===========================================================================
// helpers
// ===========================================================================
__device__ __forceinline__ void mma_f16(
    float& c0, float& c1, float& c2, float& c3,
    uint32_t a0, uint32_t a1, uint32_t a2, uint32_t a3,
    uint32_t b0, uint32_t b1)
{
    asm volatile(
        "mma.sync.aligned.m16n8k16.row.col.f32.f16.f16.f32 "
        "{%0,%1,%2,%3}, {%4,%5,%6,%7}, {%8,%9}, {%0,%1,%2,%3};"
        : "+f"(c0), "+f"(c1), "+f"(c2), "+f"(c3)
        : "r"(a0), "r"(a1), "r"(a2), "r"(a3), "r"(b0), "r"(b1));
}
__device__ __forceinline__ void ldsm_x4(
    uint32_t& r0, uint32_t& r1, uint32_t& r2, uint32_t& r3, uint32_t addr)
{
    asm volatile("ldmatrix.sync.aligned.m8n8.x4.shared.b16 {%0,%1,%2,%3}, [%4];"
                 : "=r"(r0), "=r"(r1), "=r"(r2), "=r"(r3) : "r"(addr));
}
__device__ __forceinline__ void ldsm_x4_t(
    uint32_t& r0, uint32_t& r1, uint32_t& r2, uint32_t& r3, uint32_t addr)
{
    asm volatile("ldmatrix.sync.aligned.m8n8.x4.trans.shared.b16 {%0,%1,%2,%3}, [%4];"
                 : "=r"(r0), "=r"(r1), "=r"(r2), "=r"(r3) : "r"(addr));
}
__device__ __forceinline__ uint32_t pack_h2(float a, float b) {
    __half2 h = __floats2half2_rn(a, b);
    return *(uint32_t*)&h;
}
__device__ __forceinline__ void cp_async16(uint32_t dst, const void* src) {
    asm volatile("cp.async.cg.shared.global [%0], [%1], 16;" :: "r"(dst), "l"(src));
}
__device__ __forceinline__ void cp_commit() {
    asm volatile("cp.async.commit_group;" ::: "memory");
}
__device__ __forceinline__ void cp_wait1() {
    asm volatile("cp.async.wait_group 1;" ::: "memory");
}

// ===========================================================================
// fp32 -> fp16 elementwise convert (weights), float4-vectorized
// ===========================================================================
__global__ __launch_bounds__(256) void cvt_kernel(
    const float* __restrict__ in, __half* __restrict__ out, int n4)
{
    int i = blockIdx.x * blockDim.x + threadIdx.x;
    if (i < n4) {
        float4 v = ((const float4*)in)[i];
        uint2 o;
        o.x = pack_h2(v.x, v.y);
        o.y = pack_h2(v.z, v.w);
        ((uint2*)out)[i] = o;
    }
}

// ===========================================================================
// LayerNorm: one block (256 thr) per row of 1024. fp16 out.
// ===========================================================================
__global__ __launch_bounds__(256) void ln_kernel(
    const float* __restrict__ x, const float* __restrict__ w,
    const float* __restrict__ b, __half* __restrict__ out)
{
    int row = blockIdx.x;
    int tid = threadIdx.x;
    const float4 v = ((const float4*)(x + (size_t)row * DIM))[tid];
    float s  = v.x + v.y + v.z + v.w;
    float ss = v.x*v.x + v.y*v.y + v.z*v.z + v.w*v.w;
    #pragma unroll
    for (int o = 16; o; o >>= 1) {
        s  += __shfl_xor_sync(0xffffffffu, s,  o);
        ss += __shfl_xor_sync(0xffffffffu, ss, o);
    }
    __shared__ float sh_s[8], sh_ss[8];
    int wid = tid >> 5, lane = tid & 31;
    if (lane == 0) { sh_s[wid] = s; sh_ss[wid] = ss; }
    __syncthreads();
    if (tid == 0) {
        float a = 0.f, q = 0.f;
        #pragma unroll
        for (int i = 0; i < 8; i++) { a += sh_s[i]; q += sh_ss[i]; }
        sh_s[0] = a; sh_ss[0] = q;
    }
    __syncthreads();
    float mu   = sh_s[0]  * (1.0f / DIM);
    float var  = sh_ss[0] * (1.0f / DIM) - mu * mu;
    float rstd = rsqrtf(var + LN_EPS);
    float4 w4 = ((const float4*)w)[tid];
    float4 b4 = ((const float4*)b)[tid];
    uint2 o2;
    o2.x = pack_h2((v.x - mu) * rstd * w4.x + b4.x,
                   (v.y - mu) * rstd * w4.y + b4.y);
    o2.y = pack_h2((v.z - mu) * rstd * w4.z + b4.z,
                   (v.w - mu) * rstd * w4.w + b4.w);
    ((uint2*)(out + (size_t)row * DIM))[tid] = o2;
}

// ===========================================================================
// fp16 mma GEMM v9: 3-stage cp.async pipeline (copy has a full chunk-compute
// window to land), B row-major via ldmatrix.trans. CTA tile 128x64, BK=64,
// dynamic smem 82944 B, 2 CTAs/SM. 256 threads, 8 warps 4m x 2n.
// MODE 0: C fp32. MODE 1: C fp16 + fused q/k l2norm (bx<32; one head/tile).
// ===========================================================================
#define HKC 64
#define HSTR 72
#define GEMM_SMEM (3 * (128 + 64) * HSTR * 2)   // 82944 B

template<int MODE>
__global__ __launch_bounds__(256, 2) void gemm_fp16_kernel(
    const __half* __restrict__ A, const __half* __restrict__ B,
    float* __restrict__ Cf, __half* __restrict__ Ch, int M, int N, int K)
{
    extern __shared__ __align__(16) __half gsm[];

    const int tid  = threadIdx.x;
    const int wid  = tid >> 5;
    const int lane = tid & 31;
    const int bx = blockIdx.x, by = blockIdx.y;
    const int wm = wid & 3;           // 0..3 (m)
    const int wn = wid >> 2;          // 0..1 (n)
    const int lg = lane >> 2;
    const int lt = lane & 3;
    const int l16  = lane & 15;
    const int lkhi = (lane >> 4) << 3;

    uint32_t sA[3], sB[3];
    {
        uint32_t base = (uint32_t)__cvta_generic_to_shared(gsm);
        #pragma unroll
        for (int i = 0; i < 3; i++) {
            sA[i] = base + (uint32_t)(i * (128 + 64) * HSTR) * 2;
            sB[i] = sA[i] + (uint32_t)(128 * HSTR) * 2;
        }
    }

    float acc[2][4][4];
    #pragma unroll
    for (int i = 0; i < 2; i++)
        #pragma unroll
        for (int j = 0; j < 4; j++)
            #pragma unroll
            for (int q = 0; q < 4; q++) acc[i][j][q] = 0.f;

    const int NC = K / HKC;                 // 16
    const int ci   = tid >> 3;              // A copy row 0..31 (x4 reps)
    const int cs8  = (tid & 7) << 3;        // A k-offset in halves
    const int cbr  = tid >> 2;              // B copy k-row 0..63
    const int cbc  = (tid & 3) << 3;        // B n segment (x2 reps)

    const __half* Asrc = A + (size_t)(by * 128 + ci) * K + cs8;
    const __half* Bsrc = B + (size_t)cbr * N + bx * 64 + cbc;
    const uint32_t cdstA = (uint32_t)(ci * HSTR + cs8) * 2;
    const uint32_t cdstB = (uint32_t)(cbr * HSTR + cbc) * 2;

    // loop-invariant per-thread ldsm offsets (relative to slot base)
    uint32_t aOff[2], bOff[2];
    #pragma unroll
    for (int mi = 0; mi < 2; mi++)
        aOff[mi] = (uint32_t)((wm * 32 + mi * 16 + l16) * HSTR + lkhi) * 2;
    #pragma unroll
    for (int np = 0; np < 2; np++)
        bOff[np] = (uint32_t)(l16 * HSTR + wn * 32 + np * 16 + lkhi) * 2;

    // prologue: chunks 0,1 -> slots 0,1 (two committed groups)
    #pragma unroll
    for (int st = 0; st < 2; st++) {
        #pragma unroll
        for (int rep = 0; rep < 4; rep++)
            cp_async16(sA[st] + cdstA + (uint32_t)(rep * 32 * HSTR) * 2,
                       Asrc + (size_t)(rep * 32) * K);
        #pragma unroll
        for (int rep = 0; rep < 2; rep++)
            cp_async16(sB[st] + cdstB + (uint32_t)(rep * 32) * 2,
                       Bsrc + rep * 32);
        cp_commit();
        Asrc += HKC;
        Bsrc += (size_t)HKC * N;
    }

    int cmp_slot = 0, cpy_slot = 2;
    for (int c = 0; c < NC; c++) {
        cp_wait1();        // chunk c resident (all but newest group done)
        __syncthreads();   // all warps done with cpy_slot's previous contents

        if (c + 2 < NC) {
            #pragma unroll
            for (int rep = 0; rep < 4; rep++)
                cp_async16(sA[cpy_slot] + cdstA + (uint32_t)(rep * 32 * HSTR) * 2,
                           Asrc + (size_t)(rep * 32) * K);
            #pragma unroll
            for (int rep = 0; rep < 2; rep++)
                cp_async16(sB[cpy_slot] + cdstB + (uint32_t)(rep * 32) * 2,
                           Bsrc + rep * 32);
            Asrc += HKC;
            Bsrc += (size_t)HKC * N;
        }
        cp_commit();       // unconditional (empty at tail) keeps accounting exact

        const uint32_t sAc = sA[cmp_slot], sBc = sB[cmp_slot];
        #pragma unroll
        for (int ks = 0; ks < 4; ks++) {
            const uint32_t koA = (uint32_t)(ks * 16) * 2;
            const uint32_t koB = (uint32_t)(ks * 16 * HSTR) * 2;
            uint32_t a[2][4];
            #pragma unroll
            for (int mi = 0; mi < 2; mi++)
                ldsm_x4(a[mi][0], a[mi][1], a[mi][2], a[mi][3], sAc + aOff[mi] + koA);
            uint32_t b[4][2];
            #pragma unroll
            for (int np = 0; np < 2; np++)
                ldsm_x4_t(b[2*np][0], b[2*np][1], b[2*np+1][0], b[2*np+1][1],
                          sBc + bOff[np] + koB);
            #pragma unroll
            for (int ni = 0; ni < 4; ni++)
                #pragma unroll
                for (int mi = 0; mi < 2; mi++)
                    mma_f16(acc[mi][ni][0], acc[mi][ni][1], acc[mi][ni][2], acc[mi][ni][3],
                            a[mi][0], a[mi][1], a[mi][2], a[mi][3], b[ni][0], b[ni][1]);
        }
        cmp_slot = (cmp_slot == 2) ? 0 : cmp_slot + 1;
        cpy_slot = (cpy_slot == 2) ? 0 : cpy_slot + 1;
    }

    if (MODE == 0) {
        #pragma unroll
        for (int mi = 0; mi < 2; mi++) {
            int row = by * 128 + wm * 32 + mi * 16 + lg;
            #pragma unroll
            for (int ni = 0; ni < 4; ni++) {
                int col = bx * 64 + wn * 32 + ni * 8 + (lt << 1);
                *(float2*)(Cf + (size_t)row * N + col)       = make_float2(acc[mi][ni][0], acc[mi][ni][1]);
                *(float2*)(Cf + (size_t)(row + 8) * N + col) = make_float2(acc[mi][ni][2], acc[mi][ni][3]);
            }
        }
    } else {
        // N-tile of 64 = exactly one head: l2-normalize q,k rows (bx<32)
        const bool donorm = (bx < 32);   // bx 0-15: q, 16-31: k, 32-47: v
        __syncthreads();
        float* red = (float*)gsm;        // [2 wn][128 rows]
        float ssl[2], ssh[2];
        #pragma unroll
        for (int mi = 0; mi < 2; mi++) {
            float a = 0.f, h = 0.f;
            #pragma unroll
            for (int ni = 0; ni < 4; ni++) {
                a += acc[mi][ni][0]*acc[mi][ni][0] + acc[mi][ni][1]*acc[mi][ni][1];
                h += acc[mi][ni][2]*acc[mi][ni][2] + acc[mi][ni][3]*acc[mi][ni][3];
            }
            a += __shfl_xor_sync(0xffffffffu, a, 1);
            a += __shfl_xor_sync(0xffffffffu, a, 2);
            h += __shfl_xor_sync(0xffffffffu, h, 1);
            h += __shfl_xor_sync(0xffffffffu, h, 2);
            ssl[mi] = a; ssh[mi] = h;
        }
        if (lt == 0) {
            #pragma unroll
            for (int mi = 0; mi < 2; mi++) {
                int rl = wm * 32 + mi * 16 + lg;
                red[wn * 128 + rl]     = ssl[mi];
                red[wn * 128 + rl + 8] = ssh[mi];
            }
        }
        __syncthreads();
        #pragma unroll
        for (int mi = 0; mi < 2; mi++) {
            int rl = wm * 32 + mi * 16 + lg;
            float il = 1.f, ih = 1.f;
            if (donorm) {
                float tl = ssl[mi] + red[(wn ^ 1) * 128 + rl];
                float th = ssh[mi] + red[(wn ^ 1) * 128 + rl + 8];
                il = 1.0f / fmaxf(sqrtf(tl), 1e-12f);
                ih = 1.0f / fmaxf(sqrtf(th), 1e-12f);
            }
            int row = by * 128 + rl;
            #pragma unroll
            for (int ni = 0; ni < 4; ni++) {
                int col = bx * 64 + wn * 32 + ni * 8 + (lt << 1);
                *(uint32_t*)(Ch + (size_t)row * N + col) =
                    pack_h2(acc[mi][ni][0] * il, acc[mi][ni][1] * il);
                *(uint32_t*)(Ch + (size_t)(row + 8) * N + col) =
                    pack_h2(acc[mi][ni][2] * ih, acc[mi][ni][3] * ih);
            }
        }
    }
}

// ===========================================================================
// Tensor-core flash attention (R14 verbatim — passing): fp16 qkv, cp.async
// double-buffered K/V, register-resident P, ldmatrix.trans V, 2 CTAs/SM.
// CTA: 128 q rows, 8 warps x 16 rows. Key tiles of 64.
// ===========================================================================
#define PH 72

__global__ __launch_bounds__(256, 2) void attn_tc_kernel(
    const __half* __restrict__ qkv, __half* __restrict__ oat)
{
    __shared__ __align__(16) __half Ks[2][64 * PH];
    __shared__ __align__(16) __half Vs[2][64 * PH];

    const int tid  = threadIdx.x;
    const int w    = tid >> 5;
    const int lane = tid & 31;
    const int lg = lane >> 2, lt = lane & 3;
    const int l16  = lane & 15;
    const int lkhi = (lane >> 4) << 3;
    const int qtIdx = gridDim.x - 1 - blockIdx.x;   // long CTAs first
    const int h = blockIdx.y, bb = blockIdx.z;
    const int row0 = qtIdx * 128;
    const size_t rowbase = (size_t)bb * NSEQ;
    const int R0 = row0 + w * 16;

    uint32_t sK[2], sV[2];
    sK[0] = (uint32_t)__cvta_generic_to_shared(&Ks[0][0]);
    sK[1] = (uint32_t)__cvta_generic_to_shared(&Ks[1][0]);
    sV[0] = (uint32_t)__cvta_generic_to_shared(&Vs[0][0]);
    sV[1] = (uint32_t)__cvta_generic_to_shared(&Vs[1][0]);

    // --- Q fragments: fp16 loads, exact x8 scale, resident all kernel ---
    uint32_t aq[4][4];
    {
        const __half2 s8 = __floats2half2_rn(8.0f, 8.0f);
        const __half* q0 = qkv + (rowbase + R0 + lg) * QKVW + h * DHEAD;
        const __half* q1 = q0 + 8 * QKVW;
        #pragma unroll
        for (int ks = 0; ks < 4; ks++) {
            int c = ks * 16 + 2 * lt;
            __half2 v;
            v = __hmul2(*(const __half2*)&q0[c], s8);     aq[ks][0] = *(uint32_t*)&v;
            v = __hmul2(*(const __half2*)&q1[c], s8);     aq[ks][1] = *(uint32_t*)&v;
            v = __hmul2(*(const __half2*)&q0[c + 8], s8); aq[ks][2] = *(uint32_t*)&v;
            v = __hmul2(*(const __half2*)&q1[c + 8], s8); aq[ks][3] = *(uint32_t*)&v;
        }
    }

    float oacc[8][4];
    #pragma unroll
    for (int ni = 0; ni < 8; ni++)
        #pragma unroll
        for (int q = 0; q < 4; q++) oacc[ni][q] = 0.f;
    float m0 = -INFINITY, m1 = -INFINITY, l0 = 0.f, l1 = 0.f;

    const int ntiles = 2 * qtIdx + 2;
    const int ci  = tid >> 3;         // kv row 0..31 (x2 reps)
    const int cs8 = (tid & 7) << 3;   // d-offset in halves

    const __half* kvsrc = qkv + (rowbase + ci) * QKVW + INNER + h * DHEAD + cs8;
    const uint32_t cdst = (uint32_t)(ci * PH + cs8) * 2;

    // prologue: tile 0 -> slot 0
    #pragma unroll
    for (int rep = 0; rep < 2; rep++) {
        const __half* src = kvsrc + (size_t)(rep * 32) * QKVW;
        cp_async16(sK[0] + cdst + (uint32_t)(rep * 32 * PH) * 2, src);
        cp_async16(sV[0] + cdst + (uint32_t)(rep * 32 * PH) * 2, src + INNER);
    }
    cp_commit();
    kvsrc += (size_t)64 * QKVW;

    for (int jt = 0; jt < ntiles; jt++) {
        const int j0 = jt * 64;
        if (jt + 1 < ntiles) {
            const int slot = (jt + 1) & 1;
            #pragma unroll
            for (int rep = 0; rep < 2; rep++) {
                const __half* src = kvsrc + (size_t)(rep * 32) * QKVW;
                cp_async16(sK[slot] + cdst + (uint32_t)(rep * 32 * PH) * 2, src);
                cp_async16(sV[slot] + cdst + (uint32_t)(rep * 32 * PH) * 2, src + INNER);
            }
            kvsrc += (size_t)64 * QKVW;
        }
        cp_commit();
        cp_wait1();
        __syncthreads();

        const int slot = jt & 1;
        if (j0 <= R0 + 15) {
            // --- scores ---
            float sacc[8][4];
            #pragma unroll
            for (int ni = 0; ni < 8; ni++)
                #pragma unroll
                for (int q = 0; q < 4; q++) sacc[ni][q] = 0.f;

            #pragma unroll
            for (int ks = 0; ks < 4; ks++) {
                const uint32_t ko = (uint32_t)(ks * 16) * 2;
                #pragma unroll
                for (int np = 0; np < 4; np++) {
                    uint32_t b0e, b0o, b1e, b1o;
                    ldsm_x4(b0e, b0o, b1e, b1o,
                            sK[slot] + (uint32_t)((np * 16 + l16) * PH + lkhi) * 2 + ko);
                    mma_f16(sacc[2*np][0], sacc[2*np][1], sacc[2*np][2], sacc[2*np][3],
                            aq[ks][0], aq[ks][1], aq[ks][2], aq[ks][3], b0e, b1e);
                    mma_f16(sacc[2*np+1][0], sacc[2*np+1][1], sacc[2*np+1][2], sacc[2*np+1][3],
                            aq[ks][0], aq[ks][1], aq[ks][2], aq[ks][3], b0o, b1o);
                }
            }

            // --- causal mask (diagonal-crossing tiles only) ---
            if (j0 + 63 > R0) {
                int ra = R0 + lg, rb = ra + 8;
                #pragma unroll
                for (int ni = 0; ni < 8; ni++) {
                    int k0c = j0 + ni * 8 + 2 * lt;
                    if (k0c     > ra) sacc[ni][0] = -INFINITY;
                    if (k0c + 1 > ra) sacc[ni][1] = -INFINITY;
                    if (k0c     > rb) sacc[ni][2] = -INFINITY;
                    if (k0c + 1 > rb) sacc[ni][3] = -INFINITY;
                }
            }

            // --- online softmax; pack P into A-fragment registers ---
            float mt0 = -INFINITY, mt1 = -INFINITY;
            #pragma unroll
            for (int ni = 0; ni < 8; ni++) {
                mt0 = fmaxf(mt0, fmaxf(sacc[ni][0], sacc[ni][1]));
                mt1 = fmaxf(mt1, fmaxf(sacc[ni][2], sacc[ni][3]));
            }
            mt0 = fmaxf(mt0, __shfl_xor_sync(0xffffffffu, mt0, 1));
            mt0 = fmaxf(mt0, __shfl_xor_sync(0xffffffffu, mt0, 2));
            mt1 = fmaxf(mt1, __shfl_xor_sync(0xffffffffu, mt1, 1));
            mt1 = fmaxf(mt1, __shfl_xor_sync(0xffffffffu, mt1, 2));
            float mn0 = fmaxf(m0, mt0), mn1 = fmaxf(m1, mt1);
            float c0f = __expf(m0 - mn0), c1f = __expf(m1 - mn1);
            m0 = mn0; m1 = mn1;

            float s0 = 0.f, s1 = 0.f;
            uint32_t pa[4][4];
            #pragma unroll
            for (int ni = 0; ni < 8; ni++) {
                __half2 h01 = __floats2half2_rn(__expf(sacc[ni][0] - m0), __expf(sacc[ni][1] - m0));
                __half2 h23 = __floats2half2_rn(__expf(sacc[ni][2] - m1), __expf(sacc[ni][3] - m1));
                float2 f01 = __half22float2(h01);
                float2 f23 = __half22float2(h23);
                s0 += f01.x + f01.y;
                s1 += f23.x + f23.y;
                int kc = ni >> 1;
                if ((ni & 1) == 0) { pa[kc][0] = *(uint32_t*)&h01; pa[kc][1] = *(uint32_t*)&h23; }
                else               { pa[kc][2] = *(uint32_t*)&h01; pa[kc][3] = *(uint32_t*)&h23; }
            }
            s0 += __shfl_xor_sync(0xffffffffu, s0, 1);
            s0 += __shfl_xor_sync(0xffffffffu, s0, 2);
            s1 += __shfl_xor_sync(0xffffffffu, s1, 1);
            s1 += __shfl_xor_sync(0xffffffffu, s1, 2);
            l0 = l0 * c0f + s0;
            l1 = l1 * c1f + s1;
            #pragma unroll
            for (int ni = 0; ni < 8; ni++) {
                oacc[ni][0] *= c0f; oacc[ni][1] *= c0f;
                oacc[ni][2] *= c1f; oacc[ni][3] *= c1f;
            }

            // --- PV: B from Vs[key][d] via ldmatrix.trans ---
            #pragma unroll
            for (int kc = 0; kc < 4; kc++) {
                #pragma unroll
                for (int np = 0; np < 4; np++) {
                    uint32_t r0, r1, r2, r3;
                    ldsm_x4_t(r0, r1, r2, r3,
                              sV[slot] + (uint32_t)((kc * 16 + l16) * PH + np * 16 + lkhi) * 2);
                    mma_f16(oacc[2*np][0], oacc[2*np][1], oacc[2*np][2], oacc[2*np][3],
                            pa[kc][0], pa[kc][1], pa[kc][2], pa[kc][3], r0, r1);
                    mma_f16(oacc[2*np+1][0], oacc[2*np+1][1], oacc[2*np+1][2], oacc[2*np+1][3],
                            pa[kc][0], pa[kc][1], pa[kc][2], pa[kc][3], r2, r3);
                }
            }
        }
        __syncthreads();   // slot may be overwritten by next iteration's cp.async
    }

    // --- epilogue: normalize, write fp16 [b, n, h*d] ---
    float il0 = 1.0f / l0, il1 = 1.0f / l1;
    __half* outa = oat + (rowbase + R0 + lg) * INNER + h * DHEAD;
    __half* outb = outa + 8 * INNER;
    #pragma unroll
    for (int ni = 0; ni < 8; ni++) {
        int col = ni * 8 + 2 * lt;
        *(uint32_t*)&outa[col] = pack_h2(oacc[ni][0] * il0, oacc[ni][1] * il0);
        *(uint32_t*)&outb[col] = pack_h2(oacc[ni][2] * il1, oacc[ni][3] * il1);
    }
}

// ===========================================================================
extern "C" void kernel_launch(void* const* d_in, const int* in_sizes, int n_in,
                              void* d_out, int out_size)
{
    const float* x    = (const float*)d_in[0];
    const float* lnw  = (const float*)d_in[1];
    const float* lnb  = (const float*)d_in[2];
    const float* Wqkv = (const float*)d_in[3];
    const float* Wout = (const float*)d_in[4];
    float* out = (float*)d_out;

    __half *xn, *qkvh, *oath, *wqkvh, *wouth;
    cudaGetSymbolAddress((void**)&xn,    g_xn_h);
    cudaGetSymbolAddress((void**)&qkvh,  g_qkv_h);
    cudaGetSymbolAddress((void**)&oath,  g_oat_h);
    cudaGetSymbolAddress((void**)&wqkvh, g_wqkvh);
    cudaGetSymbolAddress((void**)&wouth, g_wouth);

    cudaFuncSetAttribute(gemm_fp16_kernel<0>,
                         cudaFuncAttributeMaxDynamicSharedMemorySize, GEMM_SMEM);
    cudaFuncSetAttribute(gemm_fp16_kernel<1>,
                         cudaFuncAttributeMaxDynamicSharedMemorySize, GEMM_SMEM);

    ln_kernel<<<ROWS, 256>>>(x, lnw, lnb, xn);

    // fp32 -> fp16 weight converts (row-major preserved; no transpose)
    cvt_kernel<<<(DIM * QKVW / 4 + 255) / 256, 256>>>(Wqkv, wqkvh, DIM * QKVW / 4);
    cvt_kernel<<<(INNER * DIM / 4 + 255) / 256, 256>>>(Wout, wouth, INNER * DIM / 4);

    // QKV projection, fused q/k l2-normalization, fp16 out
    gemm_fp16_kernel<1><<<dim3(QKVW / 64, ROWS / 128), 256, GEMM_SMEM>>>(
        xn, wqkvh, nullptr, qkvh, ROWS, QKVW, DIM);

    attn_tc_kernel<<<dim3(NSEQ / 128, HEADS, BATCH), 256>>>(qkvh, oath);

    gemm_fp16_kernel<0><<<dim3(INNER / 64, ROWS / 128), 256, GEMM_SMEM>>>(
        oath, wouth, out, nullptr, ROWS, INNER, DIM);
}

// round 16
// speedup vs baseline: 1.0418x; 1.0418x over previous
#include <cuda_runtime.h>
#include <cuda_fp16.h>
#include <math.h>
#include <stdint.h>

#define BATCH 2
#define NSEQ  2048
#define DIM   1024
#define HEADS 16
#define DHEAD 64
#define INNER 1024
#define ROWS  (BATCH*NSEQ)   // 4096
#define QKVW  (3*INNER)      // 3072
#define LN_EPS 1e-5f

// Scratch (static device allocations — allowed)
__device__ __half g_xn_h  [(size_t)ROWS * DIM  ];
__device__ __half g_qkv_h [(size_t)ROWS * QKVW ];
__device__ __half g_oat_h [(size_t)ROWS * INNER];
__device__ __half g_wqkvh [(size_t)DIM * QKVW ];   // row-major [K, N] fp16
__device__ __half g_wouth [(size_t)INNER * DIM ];  // row-major [K, N] fp16

// ===========================================================================
// helpers
// ===========================================================================
__device__ __forceinline__ void mma_f16(
    float& c0, float& c1, float& c2, float& c3,
    uint32_t a0, uint32_t a1, uint32_t a2, uint32_t a3,
    uint32_t b0, uint32_t b1)
{
    asm volatile(
        "mma.sync.aligned.m16n8k16.row.col.f32.f16.f16.f32 "
        "{%0,%1,%2,%3}, {%4,%5,%6,%7}, {%8,%9}, {%0,%1,%2,%3};"
        : "+f"(c0), "+f"(c1), "+f"(c2), "+f"(c3)
        : "r"(a0), "r"(a1), "r"(a2), "r"(a3), "r"(b0), "r"(b1));
}
__device__ __forceinline__ void ldsm_x4(
    uint32_t& r0, uint32_t& r1, uint32_t& r2, uint32_t& r3, uint32_t addr)
{
    asm volatile("ldmatrix.sync.aligned.m8n8.x4.shared.b16 {%0,%1,%2,%3}, [%4];"
                 : "=r"(r0), "=r"(r1), "=r"(r2), "=r"(r3) : "r"(addr));
}
__device__ __forceinline__ void ldsm_x4_t(
    uint32_t& r0, uint32_t& r1, uint32_t& r2, uint32_t& r3, uint32_t addr)
{
    asm volatile("ldmatrix.sync.aligned.m8n8.x4.trans.shared.b16 {%0,%1,%2,%3}, [%4];"
                 : "=r"(r0), "=r"(r1), "=r"(r2), "=r"(r3) : "r"(addr));
}
__device__ __forceinline__ uint32_t pack_h2(float a, float b) {
    __half2 h = __floats2half2_rn(a, b);
    return *(uint32_t*)&h;
}
__device__ __forceinline__ void cp_async16(uint32_t dst, const void* src) {
    asm volatile("cp.async.cg.shared.global [%0], [%1], 16;" :: "r"(dst), "l"(src));
}
__device__ __forceinline__ void cp_commit() {
    asm volatile("cp.async.commit_group;" ::: "memory");
}
__device__ __forceinline__ void cp_wait0() {
    asm volatile("cp.async.wait_group 0;" ::: "memory");
}
__device__ __forceinline__ void cp_wait1() {
    asm volatile("cp.async.wait_group 1;" ::: "memory");
}

// ===========================================================================
// fp32 -> fp16 elementwise convert (weights), float4-vectorized
// ===========================================================================
__global__ __launch_bounds__(256) void cvt_kernel(
    const float* __restrict__ in, __half* __restrict__ out, int n4)
{
    int i = blockIdx.x * blockDim.x + threadIdx.x;
    if (i < n4) {
        float4 v = ((const float4*)in)[i];
        uint2 o;
        o.x = pack_h2(v.x, v.y);
        o.y = pack_h2(v.z, v.w);
        ((uint2*)out)[i] = o;
    }
}

// ===========================================================================
// LayerNorm: one block (256 thr) per row of 1024. fp16 out.
// ===========================================================================
__global__ __launch_bounds__(256) void ln_kernel(
    const float* __restrict__ x, const float* __restrict__ w,
    const float* __restrict__ b, __half* __restrict__ out)
{
    int row = blockIdx.x;
    int tid = threadIdx.x;
    const float4 v = ((const float4*)(x + (size_t)row * DIM))[tid];
    float s  = v.x + v.y + v.z + v.w;
    float ss = v.x*v.x + v.y*v.y + v.z*v.z + v.w*v.w;
    #pragma unroll
    for (int o = 16; o; o >>= 1) {
        s  += __shfl_xor_sync(0xffffffffu, s,  o);
        ss += __shfl_xor_sync(0xffffffffu, ss, o);
    }
    __shared__ float sh_s[8], sh_ss[8];
    int wid = tid >> 5, lane = tid & 31;
    if (lane == 0) { sh_s[wid] = s; sh_ss[wid] = ss; }
    __syncthreads();
    if (tid == 0) {
        float a = 0.f, q = 0.f;
        #pragma unroll
        for (int i = 0; i < 8; i++) { a += sh_s[i]; q += sh_ss[i]; }
        sh_s[0] = a; sh_ss[0] = q;
    }
    __syncthreads();
    float mu   = sh_s[0]  * (1.0f / DIM);
    float var  = sh_ss[0] * (1.0f / DIM) - mu * mu;
    float rstd = rsqrtf(var + LN_EPS);
    float4 w4 = ((const float4*)w)[tid];
    float4 b4 = ((const float4*)b)[tid];
    uint2 o2;
    o2.x = pack_h2((v.x - mu) * rstd * w4.x + b4.x,
                   (v.y - mu) * rstd * w4.y + b4.y);
    o2.y = pack_h2((v.z - mu) * rstd * w4.z + b4.z,
                   (v.w - mu) * rstd * w4.w + b4.w);
    ((uint2*)(out + (size_t)row * DIM))[tid] = o2;
}

// ===========================================================================
// fp16 mma GEMM v8 (R14 verbatim — local optimum): B row-major [K,N] via
// ldmatrix.trans, CTA tile 128x64, BK=64, dynamic smem 55296 B, 3 CTAs/SM,
// 2-stage cp.async. 256 threads, 8 warps 4m x 2n.
// MODE 0: C fp32. MODE 1: C fp16 + fused q/k l2norm (bx<32; one head/tile).
// ===========================================================================
#define HKC 64
#define HSTR 72
#define GEMM_SMEM ((2*128 + 2*64) * HSTR * 2)   // 55296 B

template<int MODE>
__global__ __launch_bounds__(256, 3) void gemm_fp16_kernel(
    const __half* __restrict__ A, const __half* __restrict__ B,
    float* __restrict__ Cf, __half* __restrict__ Ch, int M, int N, int K)
{
    extern __shared__ __align__(16) __half gsm[];

    const int tid  = threadIdx.x;
    const int wid  = tid >> 5;
    const int lane = tid & 31;
    const int bx = blockIdx.x, by = blockIdx.y;
    const int wm = wid & 3;           // 0..3 (m)
    const int wn = wid >> 2;          // 0..1 (n)
    const int lg = lane >> 2;
    const int lt = lane & 3;
    const int l16  = lane & 15;
    const int lkhi = (lane >> 4) << 3;

    uint32_t sA[2], sB[2];
    sA[0] = (uint32_t)__cvta_generic_to_shared(gsm);
    sA[1] = sA[0] + 128 * HSTR * 2;
    sB[0] = sA[0] + 2 * 128 * HSTR * 2;
    sB[1] = sB[0] + 64 * HSTR * 2;

    float acc[2][4][4];
    #pragma unroll
    for (int i = 0; i < 2; i++)
        #pragma unroll
        for (int j = 0; j < 4; j++)
            #pragma unroll
            for (int q = 0; q < 4; q++) acc[i][j][q] = 0.f;

    const int NC = K / HKC;                 // 16
    const int ci   = tid >> 3;              // A copy row 0..31 (x4 reps)
    const int cs8  = (tid & 7) << 3;        // A k-offset in halves
    const int cbr  = tid >> 2;              // B copy k-row 0..63
    const int cbc  = (tid & 3) << 3;        // B n segment (x2 reps)

    const __half* Asrc = A + (size_t)(by * 128 + ci) * K + cs8;
    const __half* Bsrc = B + (size_t)cbr * N + bx * 64 + cbc;
    const uint32_t cdstA = (uint32_t)(ci * HSTR + cs8) * 2;
    const uint32_t cdstB = (uint32_t)(cbr * HSTR + cbc) * 2;

    // loop-invariant per-thread ldsm offsets (relative to slot base)
    uint32_t aOff[2], bOff[2];
    #pragma unroll
    for (int mi = 0; mi < 2; mi++)
        aOff[mi] = (uint32_t)((wm * 32 + mi * 16 + l16) * HSTR + lkhi) * 2;
    #pragma unroll
    for (int np = 0; np < 2; np++)
        bOff[np] = (uint32_t)(l16 * HSTR + wn * 32 + np * 16 + lkhi) * 2;

    // prologue: chunk 0 -> slot 0
    #pragma unroll
    for (int rep = 0; rep < 4; rep++)
        cp_async16(sA[0] + cdstA + (uint32_t)(rep * 32 * HSTR) * 2,
                   Asrc + (size_t)(rep * 32) * K);
    #pragma unroll
    for (int rep = 0; rep < 2; rep++)
        cp_async16(sB[0] + cdstB + (uint32_t)(rep * 32) * 2,
                   Bsrc + rep * 32);
    cp_commit();
    Asrc += HKC;
    Bsrc += (size_t)HKC * N;

    for (int c = 0; c < NC; c++) {
        cp_wait0();
        __syncthreads();

        if (c + 1 < NC) {
            const int slot = (c + 1) & 1;
            #pragma unroll
            for (int rep = 0; rep < 4; rep++)
                cp_async16(sA[slot] + cdstA + (uint32_t)(rep * 32 * HSTR) * 2,
                           Asrc + (size_t)(rep * 32) * K);
            #pragma unroll
            for (int rep = 0; rep < 2; rep++)
                cp_async16(sB[slot] + cdstB + (uint32_t)(rep * 32) * 2,
                           Bsrc + rep * 32);
            cp_commit();
            Asrc += HKC;
            Bsrc += (size_t)HKC * N;
        }

        const uint32_t sAc = sA[c & 1], sBc = sB[c & 1];
        #pragma unroll
        for (int ks = 0; ks < 4; ks++) {
            const uint32_t koA = (uint32_t)(ks * 16) * 2;
            const uint32_t koB = (uint32_t)(ks * 16 * HSTR) * 2;
            uint32_t a[2][4];
            #pragma unroll
            for (int mi = 0; mi < 2; mi++)
                ldsm_x4(a[mi][0], a[mi][1], a[mi][2], a[mi][3], sAc + aOff[mi] + koA);
            uint32_t b[4][2];
            #pragma unroll
            for (int np = 0; np < 2; np++)
                ldsm_x4_t(b[2*np][0], b[2*np][1], b[2*np+1][0], b[2*np+1][1],
                          sBc + bOff[np] + koB);
            #pragma unroll
            for (int ni = 0; ni < 4; ni++)
                #pragma unroll
                for (int mi = 0; mi < 2; mi++)
                    mma_f16(acc[mi][ni][0], acc[mi][ni][1], acc[mi][ni][2], acc[mi][ni][3],
                            a[mi][0], a[mi][1], a[mi][2], a[mi][3], b[ni][0], b[ni][1]);
        }
    }

    if (MODE == 0) {
        #pragma unroll
        for (int mi = 0; mi < 2; mi++) {
            int row = by * 128 + wm * 32 + mi * 16 + lg;
            #pragma unroll
            for (int ni = 0; ni < 4; ni++) {
                int col = bx * 64 + wn * 32 + ni * 8 + (lt << 1);
                *(float2*)(Cf + (size_t)row * N + col)       = make_float2(acc[mi][ni][0], acc[mi][ni][1]);
                *(float2*)(Cf + (size_t)(row + 8) * N + col) = make_float2(acc[mi][ni][2], acc[mi][ni][3]);
            }
        }
    } else {
        // N-tile of 64 = exactly one head: l2-normalize q,k rows (bx<32)
        const bool donorm = (bx < 32);   // bx 0-15: q, 16-31: k, 32-47: v
        __syncthreads();
        float* red = (float*)gsm;        // [2 wn][128 rows]
        float ssl[2], ssh[2];
        #pragma unroll
        for (int mi = 0; mi < 2; mi++) {
            float a = 0.f, h = 0.f;
            #pragma unroll
            for (int ni = 0; ni < 4; ni++) {
                a += acc[mi][ni][0]*acc[mi][ni][0] + acc[mi][ni][1]*acc[mi][ni][1];
                h += acc[mi][ni][2]*acc[mi][ni][2] + acc[mi][ni][3]*acc[mi][ni][3];
            }
            a += __shfl_xor_sync(0xffffffffu, a, 1);
            a += __shfl_xor_sync(0xffffffffu, a, 2);
            h += __shfl_xor_sync(0xffffffffu, h, 1);
            h += __shfl_xor_sync(0xffffffffu, h, 2);
            ssl[mi] = a; ssh[mi] = h;
        }
        if (lt == 0) {
            #pragma unroll
            for (int mi = 0; mi < 2; mi++) {
                int rl = wm * 32 + mi * 16 + lg;
                red[wn * 128 + rl]     = ssl[mi];
                red[wn * 128 + rl + 8] = ssh[mi];
            }
        }
        __syncthreads();
        #pragma unroll
        for (int mi = 0; mi < 2; mi++) {
            int rl = wm * 32 + mi * 16 + lg;
            float il = 1.f, ih = 1.f;
            if (donorm) {
                float tl = ssl[mi] + red[(wn ^ 1) * 128 + rl];
                float th = ssh[mi] + red[(wn ^ 1) * 128 + rl + 8];
                il = 1.0f / fmaxf(sqrtf(tl), 1e-12f);
                ih = 1.0f / fmaxf(sqrtf(th), 1e-12f);
            }
            int row = by * 128 + rl;
            #pragma unroll
            for (int ni = 0; ni < 4; ni++) {
                int col = bx * 64 + wn * 32 + ni * 8 + (lt << 1);
                *(uint32_t*)(Ch + (size_t)row * N + col) =
                    pack_h2(acc[mi][ni][0] * il, acc[mi][ni][1] * il);
                *(uint32_t*)(Ch + (size_t)(row + 8) * N + col) =
                    pack_h2(acc[mi][ni][2] * ih, acc[mi][ni][3] * ih);
            }
        }
    }
}

// ===========================================================================
// Tensor-core flash attention v8: MAX-FREE softmax. Cosine-sim scores are
// bounded in [-8, 8], so p = exp(s-8)*8192 needs no running max, no
// correction, no oacc rescale. p' in [9.2e-4, 8192] — all normal fp16.
// The 8192 and the -8 shift cancel exactly in o = sum(p v)/sum(p) since l
// sums the SAME quantized p used by the PV mma.
// CTA: 128 q rows, 256 threads (8 warps x 16 rows). Key tiles of 64.
// ===========================================================================
#define PH 72

__global__ __launch_bounds__(256, 2) void attn_tc_kernel(
    const __half* __restrict__ qkv, __half* __restrict__ oat)
{
    __shared__ __align__(16) __half Ks[2][64 * PH];
    __shared__ __align__(16) __half Vs[2][64 * PH];

    const int tid  = threadIdx.x;
    const int w    = tid >> 5;
    const int lane = tid & 31;
    const int lg = lane >> 2, lt = lane & 3;
    const int l16  = lane & 15;
    const int lkhi = (lane >> 4) << 3;
    const int qtIdx = gridDim.x - 1 - blockIdx.x;   // long CTAs first
    const int h = blockIdx.y, bb = blockIdx.z;
    const int row0 = qtIdx * 128;
    const size_t rowbase = (size_t)bb * NSEQ;
    const int R0 = row0 + w * 16;

    uint32_t sK[2], sV[2];
    sK[0] = (uint32_t)__cvta_generic_to_shared(&Ks[0][0]);
    sK[1] = (uint32_t)__cvta_generic_to_shared(&Ks[1][0]);
    sV[0] = (uint32_t)__cvta_generic_to_shared(&Vs[0][0]);
    sV[1] = (uint32_t)__cvta_generic_to_shared(&Vs[1][0]);

    // --- Q fragments: fp16 loads, exact x8 scale, resident all kernel ---
    uint32_t aq[4][4];
    {
        const __half2 s8 = __floats2half2_rn(8.0f, 8.0f);
        const __half* q0 = qkv + (rowbase + R0 + lg) * QKVW + h * DHEAD;
        const __half* q1 = q0 + 8 * QKVW;
        #pragma unroll
        for (int ks = 0; ks < 4; ks++) {
            int c = ks * 16 + 2 * lt;
            __half2 v;
            v = __hmul2(*(const __half2*)&q0[c], s8);     aq[ks][0] = *(uint32_t*)&v;
            v = __hmul2(*(const __half2*)&q1[c], s8);     aq[ks][1] = *(uint32_t*)&v;
            v = __hmul2(*(const __half2*)&q0[c + 8], s8); aq[ks][2] = *(uint32_t*)&v;
            v = __hmul2(*(const __half2*)&q1[c + 8], s8); aq[ks][3] = *(uint32_t*)&v;
        }
    }

    float oacc[8][4];
    #pragma unroll
    for (int ni = 0; ni < 8; ni++)
        #pragma unroll
        for (int q = 0; q < 4; q++) oacc[ni][q] = 0.f;
    float l0 = 0.f, l1 = 0.f;

    const int ntiles = 2 * qtIdx + 2;
    const int ci  = tid >> 3;         // kv row 0..31 (x2 reps)
    const int cs8 = (tid & 7) << 3;   // d-offset in halves

    const __half* kvsrc = qkv + (rowbase + ci) * QKVW + INNER + h * DHEAD + cs8;
    const uint32_t cdst = (uint32_t)(ci * PH + cs8) * 2;

    // prologue: tile 0 -> slot 0
    #pragma unroll
    for (int rep = 0; rep < 2; rep++) {
        const __half* src = kvsrc + (size_t)(rep * 32) * QKVW;
        cp_async16(sK[0] + cdst + (uint32_t)(rep * 32 * PH) * 2, src);
        cp_async16(sV[0] + cdst + (uint32_t)(rep * 32 * PH) * 2, src + INNER);
    }
    cp_commit();
    kvsrc += (size_t)64 * QKVW;

    for (int jt = 0; jt < ntiles; jt++) {
        const int j0 = jt * 64;
        if (jt + 1 < ntiles) {
            const int slot = (jt + 1) & 1;
            #pragma unroll
            for (int rep = 0; rep < 2; rep++) {
                const __half* src = kvsrc + (size_t)(rep * 32) * QKVW;
                cp_async16(sK[slot] + cdst + (uint32_t)(rep * 32 * PH) * 2, src);
                cp_async16(sV[slot] + cdst + (uint32_t)(rep * 32 * PH) * 2, src + INNER);
            }
            kvsrc += (size_t)64 * QKVW;
        }
        cp_commit();
        cp_wait1();
        __syncthreads();

        const int slot = jt & 1;
        if (j0 <= R0 + 15) {
            // --- scores ---
            float sacc[8][4];
            #pragma unroll
            for (int ni = 0; ni < 8; ni++)
                #pragma unroll
                for (int q = 0; q < 4; q++) sacc[ni][q] = 0.f;

            #pragma unroll
            for (int ks = 0; ks < 4; ks++) {
                const uint32_t ko = (uint32_t)(ks * 16) * 2;
                #pragma unroll
                for (int np = 0; np < 4; np++) {
                    uint32_t b0e, b0o, b1e, b1o;
                    ldsm_x4(b0e, b0o, b1e, b1o,
                            sK[slot] + (uint32_t)((np * 16 + l16) * PH + lkhi) * 2 + ko);
                    mma_f16(sacc[2*np][0], sacc[2*np][1], sacc[2*np][2], sacc[2*np][3],
                            aq[ks][0], aq[ks][1], aq[ks][2], aq[ks][3], b0e, b1e);
                    mma_f16(sacc[2*np+1][0], sacc[2*np+1][1], sacc[2*np+1][2], sacc[2*np+1][3],
                            aq[ks][0], aq[ks][1], aq[ks][2], aq[ks][3], b0o, b1o);
                }
            }

            // --- causal mask (diagonal-crossing tiles only) ---
            if (j0 + 63 > R0) {
                int ra = R0 + lg, rb = ra + 8;
                #pragma unroll
                for (int ni = 0; ni < 8; ni++) {
                    int k0c = j0 + ni * 8 + 2 * lt;
                    if (k0c     > ra) sacc[ni][0] = -INFINITY;
                    if (k0c + 1 > ra) sacc[ni][1] = -INFINITY;
                    if (k0c     > rb) sacc[ni][2] = -INFINITY;
                    if (k0c + 1 > rb) sacc[ni][3] = -INFINITY;
                }
            }

            // --- MAX-FREE softmax: p = exp(s-8)*8192, packed directly into
            //     PV A-fragments; no running max, no rescale ---
            float s0 = 0.f, s1 = 0.f;
            uint32_t pa[4][4];
            #pragma unroll
            for (int ni = 0; ni < 8; ni++) {
                __half2 h01 = __floats2half2_rn(__expf(sacc[ni][0] - 8.0f) * 8192.0f,
                                                __expf(sacc[ni][1] - 8.0f) * 8192.0f);
                __half2 h23 = __floats2half2_rn(__expf(sacc[ni][2] - 8.0f) * 8192.0f,
                                                __expf(sacc[ni][3] - 8.0f) * 8192.0f);
                float2 f01 = __half22float2(h01);
                float2 f23 = __half22float2(h23);
                s0 += f01.x + f01.y;
                s1 += f23.x + f23.y;
                int kc = ni >> 1;
                if ((ni & 1) == 0) { pa[kc][0] = *(uint32_t*)&h01; pa[kc][1] = *(uint32_t*)&h23; }
                else               { pa[kc][2] = *(uint32_t*)&h01; pa[kc][3] = *(uint32_t*)&h23; }
            }
            s0 += __shfl_xor_sync(0xffffffffu, s0, 1);
            s0 += __shfl_xor_sync(0xffffffffu, s0, 2);
            s1 += __shfl_xor_sync(0xffffffffu, s1, 1);
            s1 += __shfl_xor_sync(0xffffffffu, s1, 2);
            l0 += s0;
            l1 += s1;

            // --- PV: B from Vs[key][d] via ldmatrix.trans ---
            #pragma unroll
            for (int kc = 0; kc < 4; kc++) {
                #pragma unroll
                for (int np = 0; np < 4; np++) {
                    uint32_t r0, r1, r2, r3;
                    ldsm_x4_t(r0, r1, r2, r3,
                              sV[slot] + (uint32_t)((kc * 16 + l16) * PH + np * 16 + lkhi) * 2);
                    mma_f16(oacc[2*np][0], oacc[2*np][1], oacc[2*np][2], oacc[2*np][3],
                            pa[kc][0], pa[kc][1], pa[kc][2], pa[kc][3], r0, r1);
                    mma_f16(oacc[2*np+1][0], oacc[2*np+1][1], oacc[2*np+1][2], oacc[2*np+1][3],
                            pa[kc][0], pa[kc][1], pa[kc][2], pa[kc][3], r2, r3);
                }
            }
        }
        __syncthreads();   // slot may be overwritten by next iteration's cp.async
    }

    // --- epilogue: normalize, write fp16 [b, n, h*d] ---
    float il0 = 1.0f / l0, il1 = 1.0f / l1;
    __half* outa = oat + (rowbase + R0 + lg) * INNER + h * DHEAD;
    __half* outb = outa + 8 * INNER;
    #pragma unroll
    for (int ni = 0; ni < 8; ni++) {
        int col = ni * 8 + 2 * lt;
        *(uint32_t*)&outa[col] = pack_h2(oacc[ni][0] * il0, oacc[ni][1] * il0);
        *(uint32_t*)&outb[col] = pack_h2(oacc[ni][2] * il1, oacc[ni][3] * il1);
    }
}

// ===========================================================================
extern "C" void kernel_launch(void* const* d_in, const int* in_sizes, int n_in,
                              void* d_out, int out_size)
{
    const float* x    = (const float*)d_in[0];
    const float* lnw  = (const float*)d_in[1];
    const float* lnb  = (const float*)d_in[2];
    const float* Wqkv = (const float*)d_in[3];
    const float* Wout = (const float*)d_in[4];
    float* out = (float*)d_out;

    __half *xn, *qkvh, *oath, *wqkvh, *wouth;
    cudaGetSymbolAddress((void**)&xn,    g_xn_h);
    cudaGetSymbolAddress((void**)&qkvh,  g_qkv_h);
    cudaGetSymbolAddress((void**)&oath,  g_oat_h);
    cudaGetSymbolAddress((void**)&wqkvh, g_wqkvh);
    cudaGetSymbolAddress((void**)&wouth, g_wouth);

    cudaFuncSetAttribute(gemm_fp16_kernel<0>,
                         cudaFuncAttributeMaxDynamicSharedMemorySize, GEMM_SMEM);
    cudaFuncSetAttribute(gemm_fp16_kernel<1>,
                         cudaFuncAttributeMaxDynamicSharedMemorySize, GEMM_SMEM);

    ln_kernel<<<ROWS, 256>>>(x, lnw, lnb, xn);

    // fp32 -> fp16 weight converts (row-major preserved; no transpose)
    cvt_kernel<<<(DIM * QKVW / 4 + 255) / 256, 256>>>(Wqkv, wqkvh, DIM * QKVW / 4);
    cvt_kernel<<<(INNER * DIM / 4 + 255) / 256, 256>>>(Wout, wouth, INNER * DIM / 4);

    // QKV projection, fused q/k l2-normalization, fp16 out
    gemm_fp16_kernel<1><<<dim3(QKVW / 64, ROWS / 128), 256, GEMM_SMEM>>>(
        xn, wqkvh, nullptr, qkvh, ROWS, QKVW, DIM);

    attn_tc_kernel<<<dim3(NSEQ / 128, HEADS, BATCH), 256>>>(qkvh, oath);

    gemm_fp16_kernel<0><<<dim3(INNER / 64, ROWS / 128), 256, GEMM_SMEM>>>(
        oath, wouth, out, nullptr, ROWS, INNER, DIM);
}